// round 14
// baseline (speedup 1.0000x reference)
#include <cuda_runtime.h>
#include <math.h>

// ---------------------------------------------------------------------------
// HybridModel: conv1(3->16)+relu -> conv2(16->8)+relu -> fc(8192->4)
//              -> 4-qubit quantum sim -> fc2(4->8192)
//              -> dconv1(8->16)+relu -> dconv2(16->3)+sigmoid
// B = 2048, images 32x32, all convs 3x3 SAME.
// R6-R13: weights repacked (k0) to [co][ci][ky][4] float4 -> 1 vector load
// per (co,ci,ky) instead of 3 scalar loads; rows loaded as float2; fc tail as
// LDG.128. Targets the measured issue-bound profile (fma 41.8%, issue 49.8%).
// ---------------------------------------------------------------------------

#define PW 34
#define PP 1156   // 34*34 padded plane
#define HALO 132  // border elements per plane

__device__ float g_ang[4096 * 4];
__device__ float g_q[4096 * 4];

// Padded weights: [co][ci][ky][4] (kx in .x/.y/.z, .w unused)
__device__ float g_pw1[16 * 3 * 3 * 4];    // conv1
__device__ float g_pw2[8 * 16 * 3 * 4];    // conv2
__device__ float g_pwd1[16 * 8 * 3 * 4];   // dconv1
__device__ float g_pwd2[3 * 16 * 3 * 4];   // dconv2

__global__ void k0_repack(const float* __restrict__ w1, const float* __restrict__ w2,
                          const float* __restrict__ wd1, const float* __restrict__ wd2)
{
    int t = threadIdx.x;
    for (int i = t; i < 16 * 3 * 9; i += 256) {
        int kx = i % 3, ky = (i / 3) % 3, rest = i / 9;
        g_pw1[(rest * 3 + ky) * 4 + kx] = w1[i];
    }
    for (int i = t; i < 8 * 16 * 9; i += 256) {
        int kx = i % 3, ky = (i / 3) % 3, rest = i / 9;
        g_pw2[(rest * 3 + ky) * 4 + kx] = w2[i];
    }
    for (int i = t; i < 16 * 8 * 9; i += 256) {
        int kx = i % 3, ky = (i / 3) % 3, rest = i / 9;
        g_pwd1[(rest * 3 + ky) * 4 + kx] = wd1[i];
    }
    for (int i = t; i < 3 * 16 * 9; i += 256) {
        int kx = i % 3, ky = (i / 3) % 3, rest = i / 9;
        g_pwd2[(rest * 3 + ky) * 4 + kx] = wd2[i];
    }
}

// Zero only the 1-element border of nplanes consecutive padded planes.
__device__ __forceinline__ void zero_halo(float* base, int nplanes, int tid)
{
    for (int i = tid; i < nplanes * HALO; i += 256) {
        int pl = i / HALO, h = i - pl * HALO;
        int pos;
        if (h < 34)       pos = h;
        else if (h < 68)  pos = 33 * PW + (h - 34);
        else if (h < 100) pos = (h - 68 + 1) * PW;
        else              pos = (h - 100 + 1) * PW + 33;
        base[pl * PP + pos] = 0.f;
    }
}

// 3x3 conv over padded smem planes, COUT<=8 register tile, vectorized loads.
// w4 layout: [co][ci][ky] float4.  WSM: weights from smem, else __ldg gmem.
template<int CIN, int COUT, bool WSM>
__device__ __forceinline__ void conv3x3_c8v(
    const float* __restrict__ in,
    const float4* __restrict__ w4,
    const float* __restrict__ bias,
    float acc[COUT][4], int y, int xg)
{
    #pragma unroll
    for (int co = 0; co < COUT; co++) {
        float bb = WSM ? bias[co] : __ldg(&bias[co]);
        #pragma unroll
        for (int px = 0; px < 4; px++) acc[co][px] = bb;
    }
    #pragma unroll
    for (int ci = 0; ci < CIN; ci++) {
        #pragma unroll
        for (int ky = 0; ky < 3; ky++) {
            const float2* row = (const float2*)&in[ci * PP + (y + ky) * PW + xg];
            float2 p0 = row[0], p1 = row[1], p2 = row[2];
            float v0 = p0.x, v1 = p0.y, v2 = p1.x;
            float v3 = p1.y, v4 = p2.x, v5 = p2.y;
            #pragma unroll
            for (int co = 0; co < COUT; co++) {
                float4 wv = WSM ? w4[(co * CIN + ci) * 3 + ky]
                                : __ldg(&w4[(co * CIN + ci) * 3 + ky]);
                acc[co][0] += v0 * wv.x + v1 * wv.y + v2 * wv.z;
                acc[co][1] += v1 * wv.x + v2 * wv.y + v3 * wv.z;
                acc[co][2] += v2 * wv.x + v3 * wv.y + v4 * wv.z;
                acc[co][3] += v3 * wv.x + v4 * wv.y + v5 * wv.z;
            }
        }
    }
}

// ---------------------------------------------------------------------------
// K1: conv1 + relu + conv2 + relu + fc  ->  g_ang[b][0..3]
// smem: xin 3*PP | h1 16*PP | pw1 576 | pw2 1536 | b1 16 | b2 8 | red 32
// ---------------------------------------------------------------------------
__global__ __launch_bounds__(256, 2)
void k1_encoder(const float* __restrict__ x,
                const float* __restrict__ b1, const float* __restrict__ b2,
                const float* __restrict__ fcw, const float* __restrict__ fcb)
{
    extern __shared__ float sm[];
    float* xin  = sm;                 // 3468
    float* h1   = sm + 3468;          // 18496
    float* sw1p = sm + 21964;         // 576  (16B aligned)
    float* sw2p = sm + 22540;         // 1536 (16B aligned)
    float* sb1  = sm + 24076;         // 16
    float* sb2  = sm + 24092;         // 8
    float* red  = sm + 24100;         // 32

    const int b = blockIdx.x;
    const int tid = threadIdx.x;

    zero_halo(xin, 3, tid);
    zero_halo(h1, 16, tid);

    const float* xb = x + (size_t)b * 3072;
    for (int i = tid; i < 3072; i += 256) {
        int c = i >> 10, p = i & 1023;
        xin[c * PP + ((p >> 5) + 1) * PW + (p & 31) + 1] = xb[i];
    }
    for (int i = tid; i < 576; i += 256)  sw1p[i] = g_pw1[i];
    for (int i = tid; i < 1536; i += 256) sw2p[i] = g_pw2[i];
    if (tid < 16) sb1[tid] = b1[tid];
    if (tid < 8)  sb2[tid] = b2[tid];
    __syncthreads();

    const int y  = tid >> 3;
    const int xg = (tid & 7) << 2;

    // conv1: 3 -> 16 in two 8-channel halves, relu, into padded h1
    #pragma unroll
    for (int half = 0; half < 2; half++) {
        float acc[8][4];
        conv3x3_c8v<3, 8, true>(xin, (const float4*)sw1p + half * 8 * 3 * 3,
                                sb1 + half * 8, acc, y, xg);
        #pragma unroll
        for (int co = 0; co < 8; co++) {
            float* hp = &h1[(half * 8 + co) * PP + (y + 1) * PW + xg + 1];
            #pragma unroll
            for (int px = 0; px < 4; px++) hp[px] = fmaxf(acc[co][px], 0.f);
        }
    }
    __syncthreads();

    // conv2: 16 -> 8, relu, fused fc partials (h2 never hits gmem)
    float ap0 = 0.f, ap1 = 0.f, ap2 = 0.f, ap3 = 0.f;
    {
        float acc[8][4];
        conv3x3_c8v<16, 8, true>(h1, (const float4*)sw2p, sb2, acc, y, xg);
        #pragma unroll
        for (int co = 0; co < 8; co++) {
            float4 hv;
            hv.x = fmaxf(acc[co][0], 0.f);
            hv.y = fmaxf(acc[co][1], 0.f);
            hv.z = fmaxf(acc[co][2], 0.f);
            hv.w = fmaxf(acc[co][3], 0.f);
            int j = co * 1024 + y * 32 + xg;
            float4 wa = __ldg((const float4*)(fcw + j));
            float4 wb = __ldg((const float4*)(fcw + 8192 + j));
            float4 wc = __ldg((const float4*)(fcw + 16384 + j));
            float4 wd = __ldg((const float4*)(fcw + 24576 + j));
            ap0 += hv.x * wa.x + hv.y * wa.y + hv.z * wa.z + hv.w * wa.w;
            ap1 += hv.x * wb.x + hv.y * wb.y + hv.z * wb.z + hv.w * wb.w;
            ap2 += hv.x * wc.x + hv.y * wc.y + hv.z * wc.z + hv.w * wc.w;
            ap3 += hv.x * wd.x + hv.y * wd.y + hv.z * wd.z + hv.w * wd.w;
        }
    }
    // block reduce the 4 fc partials
    #pragma unroll
    for (int off = 16; off; off >>= 1) {
        ap0 += __shfl_xor_sync(0xFFFFFFFFu, ap0, off);
        ap1 += __shfl_xor_sync(0xFFFFFFFFu, ap1, off);
        ap2 += __shfl_xor_sync(0xFFFFFFFFu, ap2, off);
        ap3 += __shfl_xor_sync(0xFFFFFFFFu, ap3, off);
    }
    int warp = tid >> 5, lane = tid & 31;
    if (lane == 0) {
        red[0 * 8 + warp] = ap0;
        red[1 * 8 + warp] = ap1;
        red[2 * 8 + warp] = ap2;
        red[3 * 8 + warp] = ap3;
    }
    __syncthreads();
    if (tid < 4) {
        float s = fcb[tid];
        #pragma unroll
        for (int wv = 0; wv < 8; wv++) s += red[tid * 8 + wv];
        g_ang[b * 4 + tid] = s;
    }
}

// ---------------------------------------------------------------------------
// K2: 4-qubit statevector sim, one thread per batch element.
// ---------------------------------------------------------------------------
__device__ __forceinline__ void apply1q(float sr[16], float si[16], int m,
    float u00r, float u00i, float u01r, float u01i,
    float u10r, float u10i, float u11r, float u11i)
{
    #pragma unroll
    for (int i = 0; i < 16; i++) {
        if (i & m) continue;
        int j = i | m;
        float ar = sr[i], ai = si[i], br = sr[j], bi = si[j];
        sr[i] = u00r * ar - u00i * ai + u01r * br - u01i * bi;
        si[i] = u00r * ai + u00i * ar + u01r * bi + u01i * br;
        sr[j] = u10r * ar - u10i * ai + u11r * br - u11i * bi;
        si[j] = u10r * ai + u10i * ar + u11r * bi + u11i * br;
    }
}

__global__ void k2_quantum(const float* __restrict__ qw, int nb)
{
    int b = blockIdx.x * blockDim.x + threadIdx.x;
    if (b >= nb) return;

    float sr[16], si[16];
    #pragma unroll
    for (int i = 0; i < 16; i++) { sr[i] = 0.f; si[i] = 0.f; }
    sr[0] = 1.f;

    // AngleEmbedding: RX(ang[w]) on wire w
    #pragma unroll
    for (int w = 0; w < 4; w++) {
        float a = g_ang[b * 4 + w] * 0.5f;
        float c = cosf(a), s = sinf(a);
        apply1q(sr, si, 1 << (3 - w),
                c, 0.f, 0.f, -s,
                0.f, -s, c, 0.f);
    }

    // StronglyEntanglingLayers
    #pragma unroll
    for (int l = 0; l < 3; l++) {
        #pragma unroll
        for (int w = 0; w < 4; w++) {
            float phi   = qw[(l * 4 + w) * 3 + 0];
            float theta = qw[(l * 4 + w) * 3 + 1];
            float omega = qw[(l * 4 + w) * 3 + 2];
            float ct = cosf(theta * 0.5f), st = sinf(theta * 0.5f);
            float a = (phi + omega) * 0.5f, d = (phi - omega) * 0.5f;
            float ca = cosf(a), sa = sinf(a), cd = cosf(d), sd = sinf(d);
            apply1q(sr, si, 1 << (3 - w),
                    ca * ct, -sa * ct,
                    -cd * st, -sd * st,
                    cd * st, -sd * st,
                    ca * ct,  sa * ct);
        }
        const int r = (l % 3) + 1;
        #pragma unroll
        for (int w = 0; w < 4; w++) {
            int cm = 1 << (3 - w);
            int tm = 1 << (3 - ((w + r) & 3));
            #pragma unroll
            for (int i = 0; i < 16; i++) {
                if ((i & cm) && !(i & tm)) {
                    int j = i | tm;
                    float tr = sr[i], ti = si[i];
                    sr[i] = sr[j]; si[i] = si[j];
                    sr[j] = tr;    si[j] = ti;
                }
            }
        }
    }

    // PauliZ expectation values
    #pragma unroll
    for (int w = 0; w < 4; w++) {
        int m = 1 << (3 - w);
        float e = 0.f;
        #pragma unroll
        for (int i = 0; i < 16; i++) {
            float p = sr[i] * sr[i] + si[i] * si[i];
            e += (i & m) ? -p : p;
        }
        g_q[b * 4 + w] = e;
    }
}

// ---------------------------------------------------------------------------
// K3: fc2 -> dconv1+relu -> dconv2+sigmoid  (one block per image)
// smem: g 8*PP | mmb 16*PP | sq 4  (weights via uniform LDG.128 from repack)
// ---------------------------------------------------------------------------
__global__ __launch_bounds__(256, 2)
void k3_decoder(const float* __restrict__ f2w, const float* __restrict__ f2b,
                const float* __restrict__ bd1, const float* __restrict__ bd2,
                float* __restrict__ out)
{
    extern __shared__ float sm[];
    float* g   = sm;                 // 9248
    float* mmb = sm + 9248;          // 18496
    float* sq  = sm + 27744;         // 4

    const int b = blockIdx.x;
    const int tid = threadIdx.x;

    zero_halo(g, 8, tid);
    zero_halo(mmb, 16, tid);
    if (tid < 4) sq[tid] = g_q[b * 4 + tid];
    __syncthreads();

    // fc2: (4) -> (8192), into padded g
    {
        float q0 = sq[0], q1 = sq[1], q2 = sq[2], q3 = sq[3];
        const float4* fw4 = (const float4*)f2w;
        for (int i = tid; i < 8192; i += 256) {
            float4 w4 = __ldg(&fw4[i]);
            float v = q0 * w4.x + q1 * w4.y + q2 * w4.z + q3 * w4.w + __ldg(&f2b[i]);
            int c = i >> 10, p = i & 1023;
            g[c * PP + ((p >> 5) + 1) * PW + (p & 31) + 1] = v;
        }
    }
    __syncthreads();

    const int y  = tid >> 3;
    const int xg = (tid & 7) << 2;

    // dconv1: 8 -> 16 in two 8-channel halves, relu
    #pragma unroll
    for (int half = 0; half < 2; half++) {
        float acc[8][4];
        conv3x3_c8v<8, 8, false>(g, (const float4*)g_pwd1 + half * 8 * 8 * 3,
                                 bd1 + half * 8, acc, y, xg);
        #pragma unroll
        for (int co = 0; co < 8; co++) {
            float* hp = &mmb[(half * 8 + co) * PP + (y + 1) * PW + xg + 1];
            #pragma unroll
            for (int px = 0; px < 4; px++) hp[px] = fmaxf(acc[co][px], 0.f);
        }
    }
    __syncthreads();

    // dconv2: 16 -> 3, sigmoid, final output
    {
        float acc[3][4];
        conv3x3_c8v<16, 3, false>(mmb, (const float4*)g_pwd2, bd2, acc, y, xg);
        float* ob = out + (size_t)b * 3072;
        #pragma unroll
        for (int co = 0; co < 3; co++) {
            #pragma unroll
            for (int px = 0; px < 4; px++) {
                float v = acc[co][px];
                ob[co * 1024 + y * 32 + xg + px] = 1.f / (1.f + __expf(-v));
            }
        }
    }
}

// ---------------------------------------------------------------------------
extern "C" void kernel_launch(void* const* d_in, const int* in_sizes, int n_in,
                              void* d_out, int out_size)
{
    const float* x       = (const float*)d_in[0];
    const float* conv1_w = (const float*)d_in[1];
    const float* conv1_b = (const float*)d_in[2];
    const float* conv2_w = (const float*)d_in[3];
    const float* conv2_b = (const float*)d_in[4];
    const float* fc_w    = (const float*)d_in[5];
    const float* fc_b    = (const float*)d_in[6];
    const float* q_w     = (const float*)d_in[7];
    const float* fc2_w   = (const float*)d_in[8];
    const float* fc2_b   = (const float*)d_in[9];
    const float* dconv1_w = (const float*)d_in[10];
    const float* dconv1_b = (const float*)d_in[11];
    const float* dconv2_w = (const float*)d_in[12];
    const float* dconv2_b = (const float*)d_in[13];
    float* out = (float*)d_out;

    const int nb = in_sizes[0] / 3072;

    const int k1_smem = 24132 * 4;   // 96528 B  (2 CTAs/SM)
    const int k3_smem = 27748 * 4;   // 110992 B (2 CTAs/SM)
    cudaFuncSetAttribute(k1_encoder, cudaFuncAttributeMaxDynamicSharedMemorySize, k1_smem);
    cudaFuncSetAttribute(k3_decoder, cudaFuncAttributeMaxDynamicSharedMemorySize, k3_smem);

    k0_repack<<<1, 256>>>(conv1_w, conv2_w, dconv1_w, dconv2_w);
    k1_encoder<<<nb, 256, k1_smem>>>(x, conv1_b, conv2_b, fc_w, fc_b);
    k2_quantum<<<(nb + 255) / 256, 256>>>(q_w, nb);
    k3_decoder<<<nb, 256, k3_smem>>>(fc2_w, fc2_b, dconv1_b, dconv2_b, out);
}